// round 9
// baseline (speedup 1.0000x reference)
#include <cuda_runtime.h>
#include <cuda_fp16.h>
#include <cstdint>

// ============================================================================
// Problem constants
// ============================================================================
#define PADV (-10000.0f)
static constexpr int BB = 512;
static constexpr int NN = 2048;
static constexpr int FF = 16;
static constexpr int HH = 128;
static constexpr int TILES_PER_B = NN / 128;         // 16
static constexpr int NSLOTS = BB * TILES_PER_B;      // 8192
static constexpr int PHI_GRID = 148;
static constexpr int PHI_THREADS = 512;              // 16 warps

// ============================================================================
// Device globals (scratch; allocation-free rule)
// ============================================================================
__device__ int   g_len[BB];
__device__ int   g_ticket;
__device__ int   g_nwork;
__device__ int   g_work[NSLOTS];
__device__ float g_partial[(size_t)NSLOTS * HH];     // partial pooled sums

// ============================================================================
// SMEM layout (dynamic, phi kernel) — 1 CTA/SM, ~183 KB
// W1..W3: fp16 W[n][k], row stride 256B, 16B-chunk XOR swizzle
// W0/A2 : fp16, row stride 48B (conflict-free for ldmatrix, no swizzle)
// ============================================================================
static constexpr int W1_OFF   = 0;
static constexpr int W2_OFF   = 32768;
static constexpr int W3_OFF   = 65536;
static constexpr int W0_OFF   = 98304;    // 128 n-rows x 48B = 6144
static constexpr int A2_OFF   = 104448;   // 128 rows x 48B   = 6144 (x tile fp16)
static constexpr int AP0_OFF  = 110592;   // ping activation, 32 KB
static constexpr int AP1_OFF  = 143360;   // pong activation, 32 KB
static constexpr int BIAS_OFF = 176128;   // 4 x 128 fp32
static constexpr int RED_OFF  = 178176;   // 8 x 128 fp32
static constexpr int SLOT_OFF = 182272;
static constexpr int SMEM_TOTAL = 182784;

// ============================================================================
// PTX helpers (arch-generic: ldmatrix + mma.sync fp16)
// ============================================================================
__device__ __forceinline__ uint32_t smem_to_u32(const void* smem_ptr) {
    uint32_t addr;
    asm("{ .reg .u64 tmp; cvta.to.shared.u64 tmp, %1; cvt.u32.u64 %0, tmp; }"
        : "=r"(addr) : "l"(smem_ptr));
    return addr;
}

__device__ __forceinline__ void ldsm4(uint32_t (&r)[4], uint32_t addr) {
    asm volatile("ldmatrix.sync.aligned.m8n8.x4.shared.b16 {%0,%1,%2,%3}, [%4];"
        : "=r"(r[0]), "=r"(r[1]), "=r"(r[2]), "=r"(r[3]) : "r"(addr));
}

__device__ __forceinline__ void mma16816(float (&c)[4], const uint32_t (&a)[4],
                                         uint32_t b0, uint32_t b1) {
    asm volatile(
        "mma.sync.aligned.m16n8k16.row.col.f32.f16.f16.f32 "
        "{%0,%1,%2,%3}, {%4,%5,%6,%7}, {%8,%9}, {%0,%1,%2,%3};"
        : "+f"(c[0]), "+f"(c[1]), "+f"(c[2]), "+f"(c[3])
        : "r"(a[0]), "r"(a[1]), "r"(a[2]), "r"(a[3]), "r"(b0), "r"(b1));
}

// pack (even, odd) floats -> f16x2 (lo = even, hi = odd), saturate-to-finite
__device__ __forceinline__ uint32_t pack_f16x2(float e, float o) {
    uint32_t r;
    asm("cvt.rn.satfinite.f16x2.f32 %0, %1, %2;" : "=r"(r) : "f"(o), "f"(e));
    return r;
}

// swizzled byte offset inside a [128 rows x 256B] matrix: (row, 2-byte col k)
__device__ __forceinline__ uint32_t mswz(int row, int k) {
    return (uint32_t)row * 256u + (((uint32_t)k * 2u) ^ (((uint32_t)row & 7u) << 4));
}

// ============================================================================
// Kernel 1: lengths — fanout-16 3-round search + compact work queue + resets
// (single block, 1 thread per batch; replaces reset_kernel + old len_kernel)
// ============================================================================
__device__ __forceinline__ bool row_is_pad(const float* xb, int row) {
    float4 v = __ldg((const float4*)(xb + (size_t)row * FF));
    return (v.x == PADV) & (v.y == PADV) & (v.z == PADV) & (v.w == PADV);
}

__global__ void __launch_bounds__(512)
len_kernel(const float* __restrict__ x) {
    __shared__ int s_nt[512];
    const int b = threadIdx.x;
    const float* xb = x + (size_t)b * NN * FF;

    // round 1: granularity 128 (row 0 is never pad: len >= 1)
    unsigned m1 = 0;
    #pragma unroll
    for (int i = 1; i < 16; i++)
        m1 |= (row_is_pad(xb, i * 128) ? 1u : 0u) << i;
    int i1 = m1 ? (__ffs(m1) - 1) : 16;
    int lo = (i1 - 1) * 128;                 // probe(lo) == false

    // round 2: granularity 8 within (lo, lo+128]
    unsigned m2 = 0;
    #pragma unroll
    for (int i = 1; i < 16; i++)
        m2 |= (row_is_pad(xb, lo + i * 8) ? 1u : 0u) << i;
    int i2 = m2 ? (__ffs(m2) - 1) : 16;
    int lo2 = lo + (i2 - 1) * 8;             // probe(lo2) == false

    // round 3: granularity 1 within (lo2, lo2+8]
    unsigned m3 = 0;
    #pragma unroll
    for (int i = 1; i < 8; i++)
        m3 |= (row_is_pad(xb, lo2 + i) ? 1u : 0u) << i;
    int len = m3 ? (lo2 + __ffs(m3) - 1) : (lo2 + 8);

    g_len[b] = len;
    int nt = (len + 127) >> 7;
    s_nt[b] = nt;
    __syncthreads();

    // inclusive prefix scan over 512 (Hillis-Steele, two-phase)
    int incl = nt;
    #pragma unroll
    for (int off = 1; off < 512; off <<= 1) {
        int add = (b >= off) ? s_nt[b - off] : 0;
        __syncthreads();
        incl += add;
        s_nt[b] = incl;
        __syncthreads();
    }
    int base = incl - nt;
    for (int t = 0; t < nt; t++) g_work[base + t] = (b << 4) | t;
    if (b == 511) { g_nwork = incl; g_ticket = 0; }
}

// ============================================================================
// Kernel 2: persistent phi — fp16 mma.sync, weights in SMEM, pipelined tiles
// ============================================================================
__global__ void __launch_bounds__(PHI_THREADS, 1)
phi_kernel(const float* __restrict__ x,
           const float* __restrict__ w0, const float* __restrict__ b0,
           const float* __restrict__ w1, const float* __restrict__ b1,
           const float* __restrict__ w2, const float* __restrict__ b2,
           const float* __restrict__ w3, const float* __restrict__ b3) {
    extern __shared__ __align__(1024) char smem[];
    const int tid  = threadIdx.x;
    const int wid  = tid >> 5;
    const int lane = tid & 31;
    const int rg   = wid >> 1;      // row-group 0..7 (16 rows each)
    const int ch   = wid & 1;       // col-half 0..1 (64 cols each)
    const uint32_t smem_base = smem_to_u32(smem);

    // ---- biases to SMEM ----
    {
        float* bs = (float*)(smem + BIAS_OFF);
        if (tid < HH) {
            bs[tid]          = b0[tid];
            bs[HH + tid]     = b1[tid];
            bs[2 * HH + tid] = b2[tid];
            bs[3 * HH + tid] = b3[tid];
        }
    }
    // ---- W1..W3 -> fp16, W[n][k] swizzled layout ----
    {
        const float* Wg[3] = { w1, w2, w3 };
        const int    Wo[3] = { W1_OFF, W2_OFF, W3_OFF };
        for (int Li = 0; Li < 3; Li++) {
            const float* W = Wg[Li];
            for (int i = tid; i < HH * HH; i += PHI_THREADS) {
                int k = i >> 7, n = i & 127;        // gmem: W[k][n]
                *reinterpret_cast<__half*>(smem + Wo[Li] + mswz(n, k)) = __float2half(W[i]);
            }
        }
    }
    // ---- W0 [16][128] -> fp16 W0[n][k], 48B row stride ----
    for (int i = tid; i < FF * HH; i += PHI_THREADS) {
        int k = i >> 7, n = i & 127;
        *reinterpret_cast<__half*>(smem + W0_OFF + n * 48 + k * 2) = __float2half(w0[i]);
    }

    const float* bias = (const float*)(smem + BIAS_OFF);
    int* s_slot = (int*)(smem + SLOT_OFF);
    float* red  = (float*)(smem + RED_OFF);
    const uint32_t WB[3] = { smem_base + W1_OFF, smem_base + W2_OFF, smem_base + W3_OFF };
    const uint32_t W0b = smem_base + W0_OFF;
    const uint32_t A2b = smem_base + A2_OFF;
    const uint32_t AB[2] = { smem_base + AP0_OFF, smem_base + AP1_OFF };

    // per-thread fragment coordinates
    const int ar = rg * 16 + (lane & 15);             // ldsm A row
    const int akh = (lane >> 4) << 3;                 // ldsm A k-offset (0/8)
    const int bn = ch * 64 + (lane & 7) + ((lane >> 4) << 3);  // ldsm B n base (+p*16)
    const int bk = ((lane >> 3) & 1) << 3;            // ldsm B k-offset (0/8)
    const int r0 = rg * 16 + (lane >> 2);             // C row (frag rows r0, r0+8)
    const int cc0 = ch * 64 + (lane & 3) * 2;         // C col base (+nb*8)
    const int xrow = tid >> 2, xseg = tid & 3;        // staging coords

    const int nwork = g_nwork;

    // ---- prologue: first ticket + x prefetch ----
    if (tid == 0) *s_slot = atomicAdd(&g_ticket, 1);
    __syncthreads();                                  // also covers weight staging
    int idx = *s_slot;
    int slot = 0, valid = 0;
    float4 vx = make_float4(0.f, 0.f, 0.f, 0.f);
    if (idx < nwork) {
        slot = g_work[idx];
        int bq = slot >> 4, tq = slot & 15;
        valid = min(128, g_len[bq] - tq * 128);
        vx = __ldg((const float4*)(x + ((size_t)bq * NN + tq * 128 + xrow) * FF + xseg * 4));
    }

    while (idx < nwork) {
        // ---- stage current x tile -> A2 (fp16, 48B stride), mask invalid ----
        {
            uint32_t p0 = 0, p1 = 0;
            if (xrow < valid) { p0 = pack_f16x2(vx.x, vx.y); p1 = pack_f16x2(vx.z, vx.w); }
            *(uint32_t*)(smem + A2_OFF + xrow * 48 + xseg * 8)     = p0;
            *(uint32_t*)(smem + A2_OFF + xrow * 48 + xseg * 8 + 4) = p1;
        }
        if (tid == 0) *s_slot = atomicAdd(&g_ticket, 1);   // next ticket, published below
        __syncthreads();

        float c[8][4];

        // ---- layer 0: K=16 MMA from A2 x W0, bias0+ReLU -> AP0 ----
        {
            #pragma unroll
            for (int nb = 0; nb < 8; nb++)
                #pragma unroll
                for (int j = 0; j < 4; j++) c[nb][j] = 0.f;
            uint32_t a[4];
            ldsm4(a, A2b + ar * 48 + akh * 2);
            #pragma unroll
            for (int p = 0; p < 4; p++) {
                uint32_t bh[4];
                ldsm4(bh, W0b + (bn + p * 16) * 48 + bk * 2);
                mma16816(c[2 * p],     a, bh[0], bh[1]);
                mma16816(c[2 * p + 1], a, bh[2], bh[3]);
            }
            const float* bl_ = bias;    // b0
            #pragma unroll
            for (int nb = 0; nb < 8; nb++) {
                int col = cc0 + nb * 8;
                float be = bl_[col], bo = bl_[col + 1];
                uint32_t p0 = pack_f16x2(fmaxf(c[nb][0] + be, 0.f), fmaxf(c[nb][1] + bo, 0.f));
                uint32_t p1 = pack_f16x2(fmaxf(c[nb][2] + be, 0.f), fmaxf(c[nb][3] + bo, 0.f));
                *(uint32_t*)(smem + AP0_OFF + mswz(r0, col))     = p0;
                *(uint32_t*)(smem + AP0_OFF + mswz(r0 + 8, col)) = p1;
            }
        }
        __syncthreads();                               // publishes AP0 AND s_slot

        // ---- prefetch next tile's metadata + x (hidden under layers 1..3) ----
        const int idx_n = *s_slot;
        int slot_n = 0, valid_n = 0;
        float4 vx_n = make_float4(0.f, 0.f, 0.f, 0.f);
        if (idx_n < nwork) {
            slot_n = g_work[idx_n];
            int bq = slot_n >> 4, tq = slot_n & 15;
            valid_n = min(128, g_len[bq] - tq * 128);
            vx_n = __ldg((const float4*)(x + ((size_t)bq * NN + tq * 128 + xrow) * FF + xseg * 4));
        }

        // ---- layers 1..3: fp16 MMA, ping-pong activations ----
        #pragma unroll
        for (int L = 0; L < 3; L++) {
            const uint32_t Acur = AB[L & 1];
            #pragma unroll
            for (int nb = 0; nb < 8; nb++)
                #pragma unroll
                for (int j = 0; j < 4; j++) c[nb][j] = 0.f;

            const uint32_t Wb = WB[L];
            #pragma unroll
            for (int kb = 0; kb < 8; kb++) {
                uint32_t a[4];
                ldsm4(a, Acur + mswz(ar, kb * 16 + akh));
                #pragma unroll
                for (int p = 0; p < 4; p++) {
                    uint32_t bh[4];
                    ldsm4(bh, Wb + mswz(bn + p * 16, kb * 16 + bk));
                    mma16816(c[2 * p],     a, bh[0], bh[1]);
                    mma16816(c[2 * p + 1], a, bh[2], bh[3]);
                }
            }

            if (L < 2) {
                const float* bl_ = bias + (L + 1) * HH;
                const uint32_t Anxt = AB[(L + 1) & 1] - smem_base;
                #pragma unroll
                for (int nb = 0; nb < 8; nb++) {
                    int col = cc0 + nb * 8;
                    float be = bl_[col], bo = bl_[col + 1];
                    uint32_t p0 = pack_f16x2(fmaxf(c[nb][0] + be, 0.f), fmaxf(c[nb][1] + bo, 0.f));
                    uint32_t p1 = pack_f16x2(fmaxf(c[nb][2] + be, 0.f), fmaxf(c[nb][3] + bo, 0.f));
                    *(uint32_t*)(smem + Anxt + mswz(r0, col))     = p0;
                    *(uint32_t*)(smem + Anxt + mswz(r0 + 8, col)) = p1;
                }
                __syncthreads();
            } else {
                // final: bias + ReLU + masked column-sum (pooling partial)
                const float* b3s = bias + 3 * HH;
                const float m0 = (r0 < valid) ? 1.f : 0.f;
                const float m1 = (r0 + 8 < valid) ? 1.f : 0.f;
                #pragma unroll
                for (int nb = 0; nb < 8; nb++) {
                    int col = cc0 + nb * 8;
                    float be = b3s[col], bo = b3s[col + 1];
                    float s0 = m0 * fmaxf(c[nb][0] + be, 0.f) + m1 * fmaxf(c[nb][2] + be, 0.f);
                    float s1 = m0 * fmaxf(c[nb][1] + bo, 0.f) + m1 * fmaxf(c[nb][3] + bo, 0.f);
                    #pragma unroll
                    for (int off = 4; off < 32; off <<= 1) {
                        s0 += __shfl_xor_sync(0xFFFFFFFFu, s0, off);
                        s1 += __shfl_xor_sync(0xFFFFFFFFu, s1, off);
                    }
                    if (lane < 4) {
                        int cc = ch * 64 + nb * 8 + lane * 2;
                        red[rg * HH + cc]     = s0;
                        red[rg * HH + cc + 1] = s1;
                    }
                }
                __syncthreads();
                if (tid < HH) {
                    float s = 0.f;
                    #pragma unroll
                    for (int g = 0; g < 8; g++) s += red[g * HH + tid];
                    g_partial[(size_t)slot * HH + tid] = s;
                }
            }
        }

        idx = idx_n; slot = slot_n; valid = valid_n; vx = vx_n;
    }
}

// ============================================================================
// Kernel 3: rho (fp32 SIMT) — 4 batches per block, 4-way ILP, weights reused
// ============================================================================
__global__ void __launch_bounds__(128)
rho_kernel(const float* __restrict__ w0, const float* __restrict__ b0,
           const float* __restrict__ w1, const float* __restrict__ b1,
           const float* __restrict__ w2, const float* __restrict__ b2,
           const float* __restrict__ w3, const float* __restrict__ b3,
           float* __restrict__ out) {
    __shared__ float s_in[4][HH];
    __shared__ float s_tmp[4][HH];
    const int j = threadIdx.x;
    const int bbase = blockIdx.x * 4;

    // fixed-order pooling of per-tile partials
    #pragma unroll
    for (int bb = 0; bb < 4; bb++) {
        int b = bbase + bb;
        int nt = (g_len[b] + 127) >> 7;
        float acc = 0.f;
        for (int t = 0; t < nt; t++)
            acc += g_partial[((size_t)b * TILES_PER_B + t) * HH + j];
        s_in[bb][j] = acc;
    }
    __syncthreads();

    const float* Ws[3] = { w0, w1, w2 };
    const float* Bs[3] = { b0, b1, b2 };
    for (int L = 0; L < 3; L++) {
        const float* W = Ws[L];
        float bj = Bs[L][j];
        float a0 = bj, a1 = bj, a2 = bj, a3 = bj;
        #pragma unroll 8
        for (int k = 0; k < HH; k++) {
            float w = __ldg(W + k * HH + j);
            a0 = fmaf(s_in[0][k], w, a0);
            a1 = fmaf(s_in[1][k], w, a1);
            a2 = fmaf(s_in[2][k], w, a2);
            a3 = fmaf(s_in[3][k], w, a3);
        }
        __syncthreads();
        s_in[0][j] = fmaxf(a0, 0.f);
        s_in[1][j] = fmaxf(a1, 0.f);
        s_in[2][j] = fmaxf(a2, 0.f);
        s_in[3][j] = fmaxf(a3, 0.f);
        __syncthreads();
    }

    // output: dot with w3 + b3, one warp per batch
    float wj = __ldg(w3 + j);
    #pragma unroll
    for (int bb = 0; bb < 4; bb++) s_tmp[bb][j] = s_in[bb][j] * wj;
    __syncthreads();
    const int w = j >> 5, lane = j & 31;
    float s = s_tmp[w][lane] + s_tmp[w][lane + 32] + s_tmp[w][lane + 64] + s_tmp[w][lane + 96];
    #pragma unroll
    for (int off = 16; off > 0; off >>= 1)
        s += __shfl_xor_sync(0xFFFFFFFFu, s, off);
    if (lane == 0) out[bbase + w] = s + __ldg(b3);
}

// ============================================================================
// kernel_launch
// ============================================================================
extern "C" void kernel_launch(void* const* d_in, const int* in_sizes, int n_in,
                              void* d_out, int out_size) {
    const float* x   = (const float*)d_in[0];
    const float* pw0 = (const float*)d_in[1];
    const float* pb0 = (const float*)d_in[2];
    const float* pw1 = (const float*)d_in[3];
    const float* pb1 = (const float*)d_in[4];
    const float* pw2 = (const float*)d_in[5];
    const float* pb2 = (const float*)d_in[6];
    const float* pw3 = (const float*)d_in[7];
    const float* pb3 = (const float*)d_in[8];
    const float* rw0 = (const float*)d_in[9];
    const float* rb0 = (const float*)d_in[10];
    const float* rw1 = (const float*)d_in[11];
    const float* rb1 = (const float*)d_in[12];
    const float* rw2 = (const float*)d_in[13];
    const float* rb2 = (const float*)d_in[14];
    const float* rw3 = (const float*)d_in[15];
    const float* rb3 = (const float*)d_in[16];

    static bool attr_set = false;
    if (!attr_set) {
        cudaFuncSetAttribute(phi_kernel, cudaFuncAttributeMaxDynamicSharedMemorySize, SMEM_TOTAL);
        attr_set = true;
    }

    len_kernel<<<1, 512>>>(x);
    phi_kernel<<<PHI_GRID, PHI_THREADS, SMEM_TOTAL>>>(x, pw0, pb0, pw1, pb1, pw2, pb2, pw3, pb3);
    rho_kernel<<<BB / 4, 128>>>(rw0, rb0, rw1, rb1, rw2, rb2, rw3, rb3, (float*)d_out);
}

// round 12
// speedup vs baseline: 1.0063x; 1.0063x over previous
#include <cuda_runtime.h>
#include <cuda_fp16.h>
#include <cstdint>

// ============================================================================
// Problem constants
// ============================================================================
#define PADV (-10000.0f)
static constexpr int BB = 512;
static constexpr int NN = 2048;
static constexpr int FF = 16;
static constexpr int HH = 128;
static constexpr int TILES_PER_B = NN / 128;         // 16
static constexpr int NSLOTS = BB * TILES_PER_B;      // 8192
static constexpr int PHI_GRID = 148;
static constexpr int PHI_THREADS = 512;              // 16 warps

// ============================================================================
// Device globals (scratch; allocation-free rule)
// ============================================================================
__device__ int   g_len[BB];
__device__ int   g_ticket;
__device__ int   g_nwork;
__device__ int   g_work[NSLOTS];
__device__ float g_partial[(size_t)NSLOTS * HH];     // partial pooled sums

// ============================================================================
// SMEM layout (dynamic, phi kernel) — 1 CTA/SM, ~183 KB
// W1..W3: fp16 W[n][k], row stride 256B, 16B-chunk XOR swizzle
// W0/A2 : fp16, row stride 48B (conflict-free for ldmatrix, no swizzle)
// ============================================================================
static constexpr int W1_OFF   = 0;
static constexpr int W2_OFF   = 32768;
static constexpr int W3_OFF   = 65536;
static constexpr int W0_OFF   = 98304;    // 128 n-rows x 48B = 6144
static constexpr int A2_OFF   = 104448;   // 128 rows x 48B   = 6144 (x tile fp16)
static constexpr int AP0_OFF  = 110592;   // ping activation, 32 KB
static constexpr int AP1_OFF  = 143360;   // pong activation, 32 KB
static constexpr int BIAS_OFF = 176128;   // 4 x 128 fp32
static constexpr int RED_OFF  = 178176;   // 8 x 128 fp32
static constexpr int SLOT_OFF = 182272;
static constexpr int SMEM_TOTAL = 182784;

// ============================================================================
// PTX helpers (arch-generic: ldmatrix + mma.sync fp16)
// ============================================================================
__device__ __forceinline__ uint32_t smem_to_u32(const void* smem_ptr) {
    uint32_t addr;
    asm("{ .reg .u64 tmp; cvta.to.shared.u64 tmp, %1; cvt.u32.u64 %0, tmp; }"
        : "=r"(addr) : "l"(smem_ptr));
    return addr;
}

__device__ __forceinline__ void ldsm4(uint32_t (&r)[4], uint32_t addr) {
    asm volatile("ldmatrix.sync.aligned.m8n8.x4.shared.b16 {%0,%1,%2,%3}, [%4];"
        : "=r"(r[0]), "=r"(r[1]), "=r"(r[2]), "=r"(r[3]) : "r"(addr));
}

__device__ __forceinline__ void mma16816(float (&c)[4], const uint32_t (&a)[4],
                                         uint32_t b0, uint32_t b1) {
    asm volatile(
        "mma.sync.aligned.m16n8k16.row.col.f32.f16.f16.f32 "
        "{%0,%1,%2,%3}, {%4,%5,%6,%7}, {%8,%9}, {%0,%1,%2,%3};"
        : "+f"(c[0]), "+f"(c[1]), "+f"(c[2]), "+f"(c[3])
        : "r"(a[0]), "r"(a[1]), "r"(a[2]), "r"(a[3]), "r"(b0), "r"(b1));
}

// pack (even, odd) floats -> f16x2 (lo = even, hi = odd), saturate-to-finite
__device__ __forceinline__ uint32_t pack_f16x2(float e, float o) {
    uint32_t r;
    asm("cvt.rn.satfinite.f16x2.f32 %0, %1, %2;" : "=r"(r) : "f"(o), "f"(e));
    return r;
}

// swizzled byte offset inside a [128 rows x 256B] matrix: (row, 2-byte col k)
__device__ __forceinline__ uint32_t mswz(int row, int k) {
    return (uint32_t)row * 256u + (((uint32_t)k * 2u) ^ (((uint32_t)row & 7u) << 4));
}

// ============================================================================
// Kernel 0: reset counters (must precede len_kernel's atomics)
// ============================================================================
__global__ void reset_kernel() { g_ticket = 0; g_nwork = 0; }

// ============================================================================
// Kernel 1: lengths — warp-parallel 3-probe search + compact work queue
// (64 blocks x 8 warps: spreads L1tex wavefront load across SMs)
// ============================================================================
__device__ __forceinline__ bool row_is_pad(const float* xb, int row) {
    float4 v = __ldg((const float4*)(xb + (size_t)row * FF));
    return (v.x == PADV) & (v.y == PADV) & (v.z == PADV) & (v.w == PADV);
}

__global__ void __launch_bounds__(256)
len_kernel(const float* __restrict__ x) {
    const int wid  = threadIdx.x >> 5;
    const int lane = threadIdx.x & 31;
    const int b = blockIdx.x * 8 + wid;
    if (b >= BB) return;
    const float* xb = x + (size_t)b * NN * FF;

    // level 1: granularity 64
    bool p1 = row_is_pad(xb, lane * 64);
    unsigned m1 = __ballot_sync(0xFFFFFFFFu, p1);
    int L;                          // first_pad in (L, L+64]
    if (m1 == 0) L = 2048 - 64;
    else         L = (__ffs(m1) - 1 - 1) * 64;   // bit0 never set (len >= 1)

    // level 2: granularity 2 — probe L+1+2*lane
    bool p2 = row_is_pad(xb, L + 1 + 2 * lane);
    unsigned m2 = __ballot_sync(0xFFFFFFFFu, p2);
    int len;
    if (m2 == 0) {
        len = L + 64;
    } else {
        int t0 = __ffs(m2) - 1;
        bool pm = row_is_pad(xb, L + 2 * t0);
        unsigned mm = __ballot_sync(0xFFFFFFFFu, pm);
        len = (mm & 1u) ? (L + 2 * t0) : (L + 2 * t0 + 1);
    }
    if (lane == 0) {
        g_len[b] = len;
        int nt = (len + 127) >> 7;
        int base = atomicAdd(&g_nwork, nt);
        for (int t = 0; t < nt; t++) g_work[base + t] = (b << 4) | t;
    }
}

// ============================================================================
// Kernel 2: persistent phi — fp16 mma.sync, weights in SMEM (R7-proven core
// + warp-level skip of fully-invalid 16-row groups on partial tiles)
// ============================================================================
__global__ void __launch_bounds__(PHI_THREADS, 1)
phi_kernel(const float* __restrict__ x,
           const float* __restrict__ w0, const float* __restrict__ b0,
           const float* __restrict__ w1, const float* __restrict__ b1,
           const float* __restrict__ w2, const float* __restrict__ b2,
           const float* __restrict__ w3, const float* __restrict__ b3) {
    extern __shared__ __align__(1024) char smem[];
    const int tid  = threadIdx.x;
    const int wid  = tid >> 5;
    const int lane = tid & 31;
    const int rg   = wid >> 1;      // row-group 0..7 (16 rows each)
    const int ch   = wid & 1;       // col-half 0..1 (64 cols each)
    const uint32_t smem_base = smem_to_u32(smem);

    // ---- biases to SMEM ----
    {
        float* bs = (float*)(smem + BIAS_OFF);
        if (tid < HH) {
            bs[tid]          = b0[tid];
            bs[HH + tid]     = b1[tid];
            bs[2 * HH + tid] = b2[tid];
            bs[3 * HH + tid] = b3[tid];
        }
    }
    // ---- W1..W3 -> fp16, W[n][k] swizzled layout ----
    {
        const float* Wg[3] = { w1, w2, w3 };
        const int    Wo[3] = { W1_OFF, W2_OFF, W3_OFF };
        for (int Li = 0; Li < 3; Li++) {
            const float* W = Wg[Li];
            for (int i = tid; i < HH * HH; i += PHI_THREADS) {
                int k = i >> 7, n = i & 127;        // gmem: W[k][n]
                *reinterpret_cast<__half*>(smem + Wo[Li] + mswz(n, k)) = __float2half(W[i]);
            }
        }
    }
    // ---- W0 [16][128] -> fp16 W0[n][k], 48B row stride ----
    for (int i = tid; i < FF * HH; i += PHI_THREADS) {
        int k = i >> 7, n = i & 127;
        *reinterpret_cast<__half*>(smem + W0_OFF + n * 48 + k * 2) = __float2half(w0[i]);
    }
    __syncthreads();

    const float* bias = (const float*)(smem + BIAS_OFF);
    int* s_slot = (int*)(smem + SLOT_OFF);
    float* red  = (float*)(smem + RED_OFF);
    const uint32_t WB[3] = { smem_base + W1_OFF, smem_base + W2_OFF, smem_base + W3_OFF };
    const uint32_t W0b = smem_base + W0_OFF;
    const uint32_t A2b = smem_base + A2_OFF;
    const uint32_t AB[2] = { smem_base + AP0_OFF, smem_base + AP1_OFF };

    // per-thread fragment coordinates
    const int ar = rg * 16 + (lane & 15);             // ldsm A row
    const int akh = (lane >> 4) << 3;                 // ldsm A k-offset (0/8)
    const int bn = ch * 64 + (lane & 7) + ((lane >> 4) << 3);  // ldsm B n base (+p*16)
    const int bk = ((lane >> 3) & 1) << 3;            // ldsm B k-offset (0/8)
    const int r0 = rg * 16 + (lane >> 2);             // C row (frag rows r0, r0+8)
    const int cc0 = ch * 64 + (lane & 3) * 2;         // C col base (+nb*8)

    while (true) {
        __syncthreads();                    // protects s_slot + buffer reuse
        if (tid == 0) *s_slot = atomicAdd(&g_ticket, 1);
        __syncthreads();
        const int idx = *s_slot;
        if (idx >= g_nwork) break;
        const int slot = g_work[idx];
        const int b = slot >> 4, t = slot & 15;
        const int valid = min(128, g_len[b] - t * 128);
        const bool wact = (rg * 16 < valid);   // this warp's 16-row group has valid rows

        // ---- stage x tile -> A2 as fp16 (48B stride), zero invalid rows ----
        {
            int row = tid >> 2, seg = tid & 3;
            float4 v = __ldg((const float4*)(x + ((size_t)b * NN + t * 128 + row) * FF + seg * 4));
            uint32_t p0 = 0, p1 = 0;
            if (row < valid) { p0 = pack_f16x2(v.x, v.y); p1 = pack_f16x2(v.z, v.w); }
            *(uint32_t*)(smem + A2_OFF + row * 48 + seg * 8)     = p0;
            *(uint32_t*)(smem + A2_OFF + row * 48 + seg * 8 + 4) = p1;
        }
        __syncthreads();

        float c[8][4];

        // ---- layer 0: K=16 MMA from A2 x W0, bias0+ReLU -> AP0 ----
        if (wact) {
            #pragma unroll
            for (int nb = 0; nb < 8; nb++)
                #pragma unroll
                for (int j = 0; j < 4; j++) c[nb][j] = 0.f;
            uint32_t a[4];
            ldsm4(a, A2b + ar * 48 + akh * 2);
            #pragma unroll
            for (int p = 0; p < 4; p++) {
                uint32_t bh[4];
                ldsm4(bh, W0b + (bn + p * 16) * 48 + bk * 2);
                mma16816(c[2 * p],     a, bh[0], bh[1]);
                mma16816(c[2 * p + 1], a, bh[2], bh[3]);
            }
            const float* bl_ = bias;    // b0
            #pragma unroll
            for (int nb = 0; nb < 8; nb++) {
                int col = cc0 + nb * 8;
                float be = bl_[col], bo = bl_[col + 1];
                uint32_t p0 = pack_f16x2(fmaxf(c[nb][0] + be, 0.f), fmaxf(c[nb][1] + bo, 0.f));
                uint32_t p1 = pack_f16x2(fmaxf(c[nb][2] + be, 0.f), fmaxf(c[nb][3] + bo, 0.f));
                *(uint32_t*)(smem + AP0_OFF + mswz(r0, col))     = p0;
                *(uint32_t*)(smem + AP0_OFF + mswz(r0 + 8, col)) = p1;
            }
        }
        __syncthreads();

        // ---- layers 1..3: single-pass fp16 MMA, ping-pong activations ----
        // Rows are independent through A x W: a warp whose 16-row group is
        // entirely >= valid produces only masked-out rows -> skip its MMA work.
        // (Its A rows may hold stale finite data; they never reach valid rows.)
        #pragma unroll
        for (int L = 0; L < 3; L++) {
            const uint32_t Acur = AB[L & 1];
            const uint32_t Wb = WB[L];
            if (wact) {
                #pragma unroll
                for (int nb = 0; nb < 8; nb++)
                    #pragma unroll
                    for (int j = 0; j < 4; j++) c[nb][j] = 0.f;
                #pragma unroll
                for (int kb = 0; kb < 8; kb++) {
                    uint32_t a[4];
                    ldsm4(a, Acur + mswz(ar, kb * 16 + akh));
                    #pragma unroll
                    for (int p = 0; p < 4; p++) {
                        uint32_t bh[4];
                        ldsm4(bh, Wb + mswz(bn + p * 16, kb * 16 + bk));
                        mma16816(c[2 * p],     a, bh[0], bh[1]);
                        mma16816(c[2 * p + 1], a, bh[2], bh[3]);
                    }
                }
            }

            if (L < 2) {
                if (wact) {
                    const float* bl_ = bias + (L + 1) * HH;
                    const uint32_t Anxt = AB[(L + 1) & 1] - smem_base;
                    #pragma unroll
                    for (int nb = 0; nb < 8; nb++) {
                        int col = cc0 + nb * 8;
                        float be = bl_[col], bo = bl_[col + 1];
                        uint32_t p0 = pack_f16x2(fmaxf(c[nb][0] + be, 0.f), fmaxf(c[nb][1] + bo, 0.f));
                        uint32_t p1 = pack_f16x2(fmaxf(c[nb][2] + be, 0.f), fmaxf(c[nb][3] + bo, 0.f));
                        *(uint32_t*)(smem + Anxt + mswz(r0, col))     = p0;
                        *(uint32_t*)(smem + Anxt + mswz(r0 + 8, col)) = p1;
                    }
                }
                __syncthreads();
            } else {
                // final: bias + ReLU + masked column-sum (pooling partial)
                if (wact) {
                    const float* b3s = bias + 3 * HH;
                    const float m0 = (r0 < valid) ? 1.f : 0.f;
                    const float m1 = (r0 + 8 < valid) ? 1.f : 0.f;
                    #pragma unroll
                    for (int nb = 0; nb < 8; nb++) {
                        int col = cc0 + nb * 8;
                        float be = b3s[col], bo = b3s[col + 1];
                        float s0 = m0 * fmaxf(c[nb][0] + be, 0.f) + m1 * fmaxf(c[nb][2] + be, 0.f);
                        float s1 = m0 * fmaxf(c[nb][1] + bo, 0.f) + m1 * fmaxf(c[nb][3] + bo, 0.f);
                        #pragma unroll
                        for (int off = 4; off < 32; off <<= 1) {
                            s0 += __shfl_xor_sync(0xFFFFFFFFu, s0, off);
                            s1 += __shfl_xor_sync(0xFFFFFFFFu, s1, off);
                        }
                        if (lane < 4) {
                            int cc = ch * 64 + nb * 8 + lane * 2;
                            red[rg * HH + cc]     = s0;
                            red[rg * HH + cc + 1] = s1;
                        }
                    }
                } else {
                    // zero this row-group's reduction entries (stale otherwise)
                    if (lane < 4) {
                        #pragma unroll
                        for (int nb = 0; nb < 8; nb++) {
                            int cc = ch * 64 + nb * 8 + lane * 2;
                            red[rg * HH + cc]     = 0.f;
                            red[rg * HH + cc + 1] = 0.f;
                        }
                    }
                }
                __syncthreads();
                if (tid < HH) {
                    float s = 0.f;
                    #pragma unroll
                    for (int g = 0; g < 8; g++) s += red[g * HH + tid];
                    g_partial[(size_t)slot * HH + tid] = s;
                }
            }
        }
    }
}

// ============================================================================
// Kernel 3: rho (fp32 SIMT) — 4 batches per block, 4-way ILP, weights reused
// ============================================================================
__global__ void __launch_bounds__(128)
rho_kernel(const float* __restrict__ w0, const float* __restrict__ b0,
           const float* __restrict__ w1, const float* __restrict__ b1,
           const float* __restrict__ w2, const float* __restrict__ b2,
           const float* __restrict__ w3, const float* __restrict__ b3,
           float* __restrict__ out) {
    __shared__ float s_in[4][HH];
    __shared__ float s_tmp[4][HH];
    const int j = threadIdx.x;
    const int bbase = blockIdx.x * 4;

    // fixed-order pooling of per-tile partials
    #pragma unroll
    for (int bb = 0; bb < 4; bb++) {
        int b = bbase + bb;
        int nt = (g_len[b] + 127) >> 7;
        float acc = 0.f;
        for (int t = 0; t < nt; t++)
            acc += g_partial[((size_t)b * TILES_PER_B + t) * HH + j];
        s_in[bb][j] = acc;
    }
    __syncthreads();

    const float* Ws[3] = { w0, w1, w2 };
    const float* Bs[3] = { b0, b1, b2 };
    for (int L = 0; L < 3; L++) {
        const float* W = Ws[L];
        float bj = Bs[L][j];
        float a0 = bj, a1 = bj, a2 = bj, a3 = bj;
        #pragma unroll 8
        for (int k = 0; k < HH; k++) {
            float w = __ldg(W + k * HH + j);
            a0 = fmaf(s_in[0][k], w, a0);
            a1 = fmaf(s_in[1][k], w, a1);
            a2 = fmaf(s_in[2][k], w, a2);
            a3 = fmaf(s_in[3][k], w, a3);
        }
        __syncthreads();
        s_in[0][j] = fmaxf(a0, 0.f);
        s_in[1][j] = fmaxf(a1, 0.f);
        s_in[2][j] = fmaxf(a2, 0.f);
        s_in[3][j] = fmaxf(a3, 0.f);
        __syncthreads();
    }

    // output: dot with w3 + b3, one warp per batch
    float wj = __ldg(w3 + j);
    #pragma unroll
    for (int bb = 0; bb < 4; bb++) s_tmp[bb][j] = s_in[bb][j] * wj;
    __syncthreads();
    const int w = j >> 5, lane = j & 31;
    float s = s_tmp[w][lane] + s_tmp[w][lane + 32] + s_tmp[w][lane + 64] + s_tmp[w][lane + 96];
    #pragma unroll
    for (int off = 16; off > 0; off >>= 1)
        s += __shfl_xor_sync(0xFFFFFFFFu, s, off);
    if (lane == 0) out[bbase + w] = s + __ldg(b3);
}

// ============================================================================
// kernel_launch
// ============================================================================
extern "C" void kernel_launch(void* const* d_in, const int* in_sizes, int n_in,
                              void* d_out, int out_size) {
    const float* x   = (const float*)d_in[0];
    const float* pw0 = (const float*)d_in[1];
    const float* pb0 = (const float*)d_in[2];
    const float* pw1 = (const float*)d_in[3];
    const float* pb1 = (const float*)d_in[4];
    const float* pw2 = (const float*)d_in[5];
    const float* pb2 = (const float*)d_in[6];
    const float* pw3 = (const float*)d_in[7];
    const float* pb3 = (const float*)d_in[8];
    const float* rw0 = (const float*)d_in[9];
    const float* rb0 = (const float*)d_in[10];
    const float* rw1 = (const float*)d_in[11];
    const float* rb1 = (const float*)d_in[12];
    const float* rw2 = (const float*)d_in[13];
    const float* rb2 = (const float*)d_in[14];
    const float* rw3 = (const float*)d_in[15];
    const float* rb3 = (const float*)d_in[16];

    static bool attr_set = false;
    if (!attr_set) {
        cudaFuncSetAttribute(phi_kernel, cudaFuncAttributeMaxDynamicSharedMemorySize, SMEM_TOTAL);
        attr_set = true;
    }

    reset_kernel<<<1, 1>>>();
    len_kernel<<<BB / 8, 256>>>(x);
    phi_kernel<<<PHI_GRID, PHI_THREADS, SMEM_TOTAL>>>(x, pw0, pb0, pw1, pb1, pw2, pb2, pw3, pb3);
    rho_kernel<<<BB / 4, 128>>>(rw0, rb0, rw1, rb1, rw2, rb2, rw3, rb3, (float*)d_out);
}

// round 14
// speedup vs baseline: 1.0398x; 1.0333x over previous
#include <cuda_runtime.h>
#include <cuda_fp16.h>
#include <cstdint>

// ============================================================================
// Problem constants
// ============================================================================
#define PADV (-10000.0f)
static constexpr int BB = 512;
static constexpr int NN = 2048;
static constexpr int FF = 16;
static constexpr int HH = 128;
static constexpr int TILES_PER_B = NN / 128;         // 16
static constexpr int NSLOTS = BB * TILES_PER_B;      // 8192
static constexpr int PHI_GRID = 148;
static constexpr int PHI_THREADS = 512;              // 16 warps

// ============================================================================
// Device globals (scratch; allocation-free rule; zero-init at module load,
// and re-zeroed at the tail of rho_kernel each run)
// ============================================================================
__device__ int   g_len[BB];
__device__ int   g_ticket;
__device__ int   g_nwork;
__device__ int   g_work[NSLOTS];
__device__ float g_partial[(size_t)NSLOTS * HH];     // partial pooled sums

// ============================================================================
// SMEM layout (dynamic, phi kernel) — 1 CTA/SM, ~183 KB
// W1..W3: fp16 W[n][k], row stride 256B, 16B-chunk XOR swizzle
// W0/A2 : fp16, row stride 48B (conflict-free for ldmatrix, no swizzle)
// ============================================================================
static constexpr int W1_OFF   = 0;
static constexpr int W2_OFF   = 32768;
static constexpr int W3_OFF   = 65536;
static constexpr int W0_OFF   = 98304;    // 128 n-rows x 48B = 6144
static constexpr int A2_OFF   = 104448;   // 128 rows x 48B   = 6144 (x tile fp16)
static constexpr int AP0_OFF  = 110592;   // ping activation, 32 KB
static constexpr int AP1_OFF  = 143360;   // pong activation, 32 KB
static constexpr int BIAS_OFF = 176128;   // 4 x 128 fp32
static constexpr int RED_OFF  = 178176;   // 8 x 128 fp32
static constexpr int SLOT_OFF = 182272;
static constexpr int SMEM_TOTAL = 182784;

// ============================================================================
// PTX helpers (arch-generic: ldmatrix + mma.sync fp16)
// ============================================================================
__device__ __forceinline__ uint32_t smem_to_u32(const void* smem_ptr) {
    uint32_t addr;
    asm("{ .reg .u64 tmp; cvta.to.shared.u64 tmp, %1; cvt.u32.u64 %0, tmp; }"
        : "=r"(addr) : "l"(smem_ptr));
    return addr;
}

__device__ __forceinline__ void ldsm4(uint32_t (&r)[4], uint32_t addr) {
    asm volatile("ldmatrix.sync.aligned.m8n8.x4.shared.b16 {%0,%1,%2,%3}, [%4];"
        : "=r"(r[0]), "=r"(r[1]), "=r"(r[2]), "=r"(r[3]) : "r"(addr));
}

__device__ __forceinline__ void mma16816(float (&c)[4], const uint32_t (&a)[4],
                                         uint32_t b0, uint32_t b1) {
    asm volatile(
        "mma.sync.aligned.m16n8k16.row.col.f32.f16.f16.f32 "
        "{%0,%1,%2,%3}, {%4,%5,%6,%7}, {%8,%9}, {%0,%1,%2,%3};"
        : "+f"(c[0]), "+f"(c[1]), "+f"(c[2]), "+f"(c[3])
        : "r"(a[0]), "r"(a[1]), "r"(a[2]), "r"(a[3]), "r"(b0), "r"(b1));
}

// pack (even, odd) floats -> f16x2 (lo = even, hi = odd), saturate-to-finite
__device__ __forceinline__ uint32_t pack_f16x2(float e, float o) {
    uint32_t r;
    asm("cvt.rn.satfinite.f16x2.f32 %0, %1, %2;" : "=r"(r) : "f"(o), "f"(e));
    return r;
}

// swizzled byte offset inside a [128 rows x 256B] matrix: (row, 2-byte col k)
__device__ __forceinline__ uint32_t mswz(int row, int k) {
    return (uint32_t)row * 256u + (((uint32_t)k * 2u) ^ (((uint32_t)row & 7u) << 4));
}

// ============================================================================
// Kernel 1: lengths — warp-parallel 3-probe search + compact work queue
// (64 blocks x 8 warps: spreads L1tex wavefront load across SMs)
// ============================================================================
__device__ __forceinline__ bool row_is_pad(const float* xb, int row) {
    float4 v = __ldg((const float4*)(xb + (size_t)row * FF));
    return (v.x == PADV) & (v.y == PADV) & (v.z == PADV) & (v.w == PADV);
}

__global__ void __launch_bounds__(256)
len_kernel(const float* __restrict__ x) {
    const int wid  = threadIdx.x >> 5;
    const int lane = threadIdx.x & 31;
    const int b = blockIdx.x * 8 + wid;
    if (b >= BB) return;
    const float* xb = x + (size_t)b * NN * FF;

    // level 1: granularity 64
    bool p1 = row_is_pad(xb, lane * 64);
    unsigned m1 = __ballot_sync(0xFFFFFFFFu, p1);
    int L;                          // first_pad in (L, L+64]
    if (m1 == 0) L = 2048 - 64;
    else         L = (__ffs(m1) - 1 - 1) * 64;   // bit0 never set (len >= 1)

    // level 2: granularity 2 — probe L+1+2*lane
    bool p2 = row_is_pad(xb, L + 1 + 2 * lane);
    unsigned m2 = __ballot_sync(0xFFFFFFFFu, p2);
    int len;
    if (m2 == 0) {
        len = L + 64;
    } else {
        int t0 = __ffs(m2) - 1;
        bool pm = row_is_pad(xb, L + 2 * t0);
        unsigned mm = __ballot_sync(0xFFFFFFFFu, pm);
        len = (mm & 1u) ? (L + 2 * t0) : (L + 2 * t0 + 1);
    }
    if (lane == 0) {
        g_len[b] = len;
        int nt = (len + 127) >> 7;
        int base = atomicAdd(&g_nwork, nt);
        for (int t = 0; t < nt; t++) g_work[base + t] = (b << 4) | t;
    }
}

// ============================================================================
// Kernel 2: persistent phi — fp16 mma.sync, weights in SMEM (R7-proven core
// + warp-level skip of fully-invalid 16-row groups on partial tiles)
// ============================================================================
__global__ void __launch_bounds__(PHI_THREADS, 1)
phi_kernel(const float* __restrict__ x,
           const float* __restrict__ w0, const float* __restrict__ b0,
           const float* __restrict__ w1, const float* __restrict__ b1,
           const float* __restrict__ w2, const float* __restrict__ b2,
           const float* __restrict__ w3, const float* __restrict__ b3) {
    extern __shared__ __align__(1024) char smem[];
    const int tid  = threadIdx.x;
    const int wid  = tid >> 5;
    const int lane = tid & 31;
    const int rg   = wid >> 1;      // row-group 0..7 (16 rows each)
    const int ch   = wid & 1;       // col-half 0..1 (64 cols each)
    const uint32_t smem_base = smem_to_u32(smem);

    // ---- biases to SMEM ----
    {
        float* bs = (float*)(smem + BIAS_OFF);
        if (tid < HH) {
            bs[tid]          = b0[tid];
            bs[HH + tid]     = b1[tid];
            bs[2 * HH + tid] = b2[tid];
            bs[3 * HH + tid] = b3[tid];
        }
    }
    // ---- W1..W3 -> fp16, W[n][k] swizzled layout ----
    {
        const float* Wg[3] = { w1, w2, w3 };
        const int    Wo[3] = { W1_OFF, W2_OFF, W3_OFF };
        for (int Li = 0; Li < 3; Li++) {
            const float* W = Wg[Li];
            for (int i = tid; i < HH * HH; i += PHI_THREADS) {
                int k = i >> 7, n = i & 127;        // gmem: W[k][n]
                *reinterpret_cast<__half*>(smem + Wo[Li] + mswz(n, k)) = __float2half(W[i]);
            }
        }
    }
    // ---- W0 [16][128] -> fp16 W0[n][k], 48B row stride ----
    for (int i = tid; i < FF * HH; i += PHI_THREADS) {
        int k = i >> 7, n = i & 127;
        *reinterpret_cast<__half*>(smem + W0_OFF + n * 48 + k * 2) = __float2half(w0[i]);
    }
    __syncthreads();

    const float* bias = (const float*)(smem + BIAS_OFF);
    int* s_slot = (int*)(smem + SLOT_OFF);
    float* red  = (float*)(smem + RED_OFF);
    const uint32_t WB[3] = { smem_base + W1_OFF, smem_base + W2_OFF, smem_base + W3_OFF };
    const uint32_t W0b = smem_base + W0_OFF;
    const uint32_t A2b = smem_base + A2_OFF;
    const uint32_t AB[2] = { smem_base + AP0_OFF, smem_base + AP1_OFF };

    // per-thread fragment coordinates
    const int ar = rg * 16 + (lane & 15);             // ldsm A row
    const int akh = (lane >> 4) << 3;                 // ldsm A k-offset (0/8)
    const int bn = ch * 64 + (lane & 7) + ((lane >> 4) << 3);  // ldsm B n base (+p*16)
    const int bk = ((lane >> 3) & 1) << 3;            // ldsm B k-offset (0/8)
    const int r0 = rg * 16 + (lane >> 2);             // C row (frag rows r0, r0+8)
    const int cc0 = ch * 64 + (lane & 3) * 2;         // C col base (+nb*8)

    while (true) {
        __syncthreads();                    // protects s_slot + buffer reuse
        if (tid == 0) *s_slot = atomicAdd(&g_ticket, 1);
        __syncthreads();
        const int idx = *s_slot;
        if (idx >= g_nwork) break;
        const int slot = g_work[idx];
        const int b = slot >> 4, t = slot & 15;
        const int valid = min(128, g_len[b] - t * 128);
        const bool wact = (rg * 16 < valid);   // this warp's 16-row group has valid rows

        // ---- stage x tile -> A2 as fp16 (48B stride), zero invalid rows ----
        {
            int row = tid >> 2, seg = tid & 3;
            float4 v = __ldg((const float4*)(x + ((size_t)b * NN + t * 128 + row) * FF + seg * 4));
            uint32_t p0 = 0, p1 = 0;
            if (row < valid) { p0 = pack_f16x2(v.x, v.y); p1 = pack_f16x2(v.z, v.w); }
            *(uint32_t*)(smem + A2_OFF + row * 48 + seg * 8)     = p0;
            *(uint32_t*)(smem + A2_OFF + row * 48 + seg * 8 + 4) = p1;
        }
        __syncthreads();

        float c[8][4];

        // ---- layer 0: K=16 MMA from A2 x W0, bias0+ReLU -> AP0 ----
        if (wact) {
            #pragma unroll
            for (int nb = 0; nb < 8; nb++)
                #pragma unroll
                for (int j = 0; j < 4; j++) c[nb][j] = 0.f;
            uint32_t a[4];
            ldsm4(a, A2b + ar * 48 + akh * 2);
            #pragma unroll
            for (int p = 0; p < 4; p++) {
                uint32_t bh[4];
                ldsm4(bh, W0b + (bn + p * 16) * 48 + bk * 2);
                mma16816(c[2 * p],     a, bh[0], bh[1]);
                mma16816(c[2 * p + 1], a, bh[2], bh[3]);
            }
            const float* bl_ = bias;    // b0
            #pragma unroll
            for (int nb = 0; nb < 8; nb++) {
                int col = cc0 + nb * 8;
                float be = bl_[col], bo = bl_[col + 1];
                uint32_t p0 = pack_f16x2(fmaxf(c[nb][0] + be, 0.f), fmaxf(c[nb][1] + bo, 0.f));
                uint32_t p1 = pack_f16x2(fmaxf(c[nb][2] + be, 0.f), fmaxf(c[nb][3] + bo, 0.f));
                *(uint32_t*)(smem + AP0_OFF + mswz(r0, col))     = p0;
                *(uint32_t*)(smem + AP0_OFF + mswz(r0 + 8, col)) = p1;
            }
        }
        __syncthreads();

        // ---- layers 1..3: single-pass fp16 MMA, ping-pong activations ----
        #pragma unroll
        for (int L = 0; L < 3; L++) {
            const uint32_t Acur = AB[L & 1];
            const uint32_t Wb = WB[L];
            if (wact) {
                #pragma unroll
                for (int nb = 0; nb < 8; nb++)
                    #pragma unroll
                    for (int j = 0; j < 4; j++) c[nb][j] = 0.f;
                #pragma unroll
                for (int kb = 0; kb < 8; kb++) {
                    uint32_t a[4];
                    ldsm4(a, Acur + mswz(ar, kb * 16 + akh));
                    #pragma unroll
                    for (int p = 0; p < 4; p++) {
                        uint32_t bh[4];
                        ldsm4(bh, Wb + mswz(bn + p * 16, kb * 16 + bk));
                        mma16816(c[2 * p],     a, bh[0], bh[1]);
                        mma16816(c[2 * p + 1], a, bh[2], bh[3]);
                    }
                }
            }

            if (L < 2) {
                if (wact) {
                    const float* bl_ = bias + (L + 1) * HH;
                    const uint32_t Anxt = AB[(L + 1) & 1] - smem_base;
                    #pragma unroll
                    for (int nb = 0; nb < 8; nb++) {
                        int col = cc0 + nb * 8;
                        float be = bl_[col], bo = bl_[col + 1];
                        uint32_t p0 = pack_f16x2(fmaxf(c[nb][0] + be, 0.f), fmaxf(c[nb][1] + bo, 0.f));
                        uint32_t p1 = pack_f16x2(fmaxf(c[nb][2] + be, 0.f), fmaxf(c[nb][3] + bo, 0.f));
                        *(uint32_t*)(smem + Anxt + mswz(r0, col))     = p0;
                        *(uint32_t*)(smem + Anxt + mswz(r0 + 8, col)) = p1;
                    }
                }
                __syncthreads();
            } else {
                // final: bias + ReLU + masked column-sum (pooling partial)
                if (wact) {
                    const float* b3s = bias + 3 * HH;
                    const float m0 = (r0 < valid) ? 1.f : 0.f;
                    const float m1 = (r0 + 8 < valid) ? 1.f : 0.f;
                    #pragma unroll
                    for (int nb = 0; nb < 8; nb++) {
                        int col = cc0 + nb * 8;
                        float be = b3s[col], bo = b3s[col + 1];
                        float s0 = m0 * fmaxf(c[nb][0] + be, 0.f) + m1 * fmaxf(c[nb][2] + be, 0.f);
                        float s1 = m0 * fmaxf(c[nb][1] + bo, 0.f) + m1 * fmaxf(c[nb][3] + bo, 0.f);
                        #pragma unroll
                        for (int off = 4; off < 32; off <<= 1) {
                            s0 += __shfl_xor_sync(0xFFFFFFFFu, s0, off);
                            s1 += __shfl_xor_sync(0xFFFFFFFFu, s1, off);
                        }
                        if (lane < 4) {
                            int cc = ch * 64 + nb * 8 + lane * 2;
                            red[rg * HH + cc]     = s0;
                            red[rg * HH + cc + 1] = s1;
                        }
                    }
                } else {
                    if (lane < 4) {
                        #pragma unroll
                        for (int nb = 0; nb < 8; nb++) {
                            int cc = ch * 64 + nb * 8 + lane * 2;
                            red[rg * HH + cc]     = 0.f;
                            red[rg * HH + cc + 1] = 0.f;
                        }
                    }
                }
                __syncthreads();
                if (tid < HH) {
                    float s = 0.f;
                    #pragma unroll
                    for (int g = 0; g < 8; g++) s += red[g * HH + tid];
                    g_partial[(size_t)slot * HH + tid] = s;
                }
            }
        }
    }
}

// ============================================================================
// Kernel 3: rho (fp32 SIMT) — 1 batch/block (512 blocks), K split across 2
// thread-halves to shorten the latency chain; resets counters at the tail.
// ============================================================================
__global__ void __launch_bounds__(256)
rho_kernel(const float* __restrict__ w0, const float* __restrict__ b0,
           const float* __restrict__ w1, const float* __restrict__ b1,
           const float* __restrict__ w2, const float* __restrict__ b2,
           const float* __restrict__ w3, const float* __restrict__ b3,
           float* __restrict__ out) {
    __shared__ float s_in[HH];
    __shared__ float s_part[2][HH];
    const int b = blockIdx.x;
    const int j = threadIdx.x & 127;
    const int h = threadIdx.x >> 7;           // k-half 0/1

    // fixed-split pooling of per-tile partials (deterministic)
    {
        const int nt = (g_len[b] + 127) >> 7;
        float acc = 0.f;
        for (int t = h; t < nt; t += 2)
            acc += g_partial[((size_t)b * TILES_PER_B + t) * HH + j];
        s_part[h][j] = acc;
    }
    __syncthreads();
    if (h == 0) s_in[j] = s_part[0][j] + s_part[1][j];
    __syncthreads();

    const float* Ws[3] = { w0, w1, w2 };
    const float* Bs[3] = { b0, b1, b2 };
    #pragma unroll
    for (int L = 0; L < 3; L++) {
        const float* W = Ws[L] + (size_t)h * 64 * HH;
        float p = 0.f;
        #pragma unroll 16
        for (int kk = 0; kk < 64; kk++)
            p = fmaf(s_in[h * 64 + kk], __ldg(W + kk * HH + j), p);
        s_part[h][j] = p;
        __syncthreads();
        if (h == 0) s_in[j] = fmaxf(s_part[0][j] + s_part[1][j] + Bs[L][j], 0.f);
        __syncthreads();
    }

    // output: dot(s_in, w3) + b3, reduced by warp 0
    if (h == 0) s_part[0][j] = s_in[j] * __ldg(w3 + j);
    __syncthreads();
    if (threadIdx.x < 32) {
        const int lane = threadIdx.x;
        float s = s_part[0][lane] + s_part[0][lane + 32]
                + s_part[0][lane + 64] + s_part[0][lane + 96];
        #pragma unroll
        for (int off = 16; off > 0; off >>= 1)
            s += __shfl_xor_sync(0xFFFFFFFFu, s, off);
        if (lane == 0) out[b] = s + __ldg(b3);
    }

    // tail reset for the next graph replay (all consumers of these counters
    // ran in earlier kernels of this same stream-ordered sequence)
    if (b == 0 && threadIdx.x == 0) { g_ticket = 0; g_nwork = 0; }
}

// ============================================================================
// kernel_launch
// ============================================================================
extern "C" void kernel_launch(void* const* d_in, const int* in_sizes, int n_in,
                              void* d_out, int out_size) {
    const float* x   = (const float*)d_in[0];
    const float* pw0 = (const float*)d_in[1];
    const float* pb0 = (const float*)d_in[2];
    const float* pw1 = (const float*)d_in[3];
    const float* pb1 = (const float*)d_in[4];
    const float* pw2 = (const float*)d_in[5];
    const float* pb2 = (const float*)d_in[6];
    const float* pw3 = (const float*)d_in[7];
    const float* pb3 = (const float*)d_in[8];
    const float* rw0 = (const float*)d_in[9];
    const float* rb0 = (const float*)d_in[10];
    const float* rw1 = (const float*)d_in[11];
    const float* rb1 = (const float*)d_in[12];
    const float* rw2 = (const float*)d_in[13];
    const float* rb2 = (const float*)d_in[14];
    const float* rw3 = (const float*)d_in[15];
    const float* rb3 = (const float*)d_in[16];

    static bool attr_set = false;
    if (!attr_set) {
        cudaFuncSetAttribute(phi_kernel, cudaFuncAttributeMaxDynamicSharedMemorySize, SMEM_TOTAL);
        attr_set = true;
    }

    len_kernel<<<BB / 8, 256>>>(x);
    phi_kernel<<<PHI_GRID, PHI_THREADS, SMEM_TOTAL>>>(x, pw0, pb0, pw1, pb1, pw2, pb2, pw3, pb3);
    rho_kernel<<<BB, 256>>>(rw0, rb0, rw1, rb1, rw2, rb2, rw3, rb3, (float*)d_out);
}

// round 15
// speedup vs baseline: 1.0778x; 1.0365x over previous
#include <cuda_runtime.h>
#include <cuda_fp16.h>
#include <cstdint>

// ============================================================================
// Problem constants
// ============================================================================
#define PADV (-10000.0f)
static constexpr int BB = 512;
static constexpr int NN = 2048;
static constexpr int FF = 16;
static constexpr int HH = 128;
static constexpr int TILES2 = 32;                    // 64-row units per batch
static constexpr int NSLOTS2 = BB * TILES2;          // 16384
static constexpr int PHI_GRID = 148;
static constexpr int PHI_THREADS = 512;              // 16 warps = 2 groups x 8

// ============================================================================
// Device globals (scratch; allocation-free rule; zero-init at module load,
// re-zeroed at the tail of rho_kernel each run)
// ============================================================================
__device__ int   g_len[BB];
__device__ int   g_ticket;
__device__ int   g_nwork;
__device__ int   g_work[NSLOTS2];
__device__ float g_partial[(size_t)NSLOTS2 * HH];    // 8 MB partial pooled sums

// ============================================================================
// SMEM layout (dynamic, phi kernel) — 1 CTA/SM, ~180 KB
// W1..W3: fp16 W[n][k], row stride 256B, 16B-chunk XOR swizzle (shared)
// W0/A2 : fp16, row stride 48B (conflict-free for ldmatrix, no swizzle)
// Per-group block: A2 (64x48B), AP0/AP1 (64x256B), red (4x128 f32), slot
// ============================================================================
static constexpr int W1_OFF   = 0;
static constexpr int W2_OFF   = 32768;
static constexpr int W3_OFF   = 65536;
static constexpr int W0_OFF   = 98304;    // 128 n-rows x 48B = 6144
static constexpr int GRP_OFF  = 104448;   // two group blocks follow
static constexpr int GRP_SZ   = 38912;    // 1024-aligned per-group block
static constexpr int GA2_OFF  = 0;        // + 3072
static constexpr int GAP0_OFF = 3072;     // + 16384
static constexpr int GAP1_OFF = 19456;    // + 16384
static constexpr int GRED_OFF = 35840;    // + 2048
static constexpr int GSLOT_OFF= 37888;    // + 64
static constexpr int BIAS_OFF = GRP_OFF + 2 * GRP_SZ;   // 182272, 2048B
static constexpr int SMEM_TOTAL = BIAS_OFF + 2048;      // 184320

// ============================================================================
// PTX helpers (arch-generic: ldmatrix + mma.sync fp16)
// ============================================================================
__device__ __forceinline__ uint32_t smem_to_u32(const void* smem_ptr) {
    uint32_t addr;
    asm("{ .reg .u64 tmp; cvta.to.shared.u64 tmp, %1; cvt.u32.u64 %0, tmp; }"
        : "=r"(addr) : "l"(smem_ptr));
    return addr;
}

__device__ __forceinline__ void ldsm4(uint32_t (&r)[4], uint32_t addr) {
    asm volatile("ldmatrix.sync.aligned.m8n8.x4.shared.b16 {%0,%1,%2,%3}, [%4];"
        : "=r"(r[0]), "=r"(r[1]), "=r"(r[2]), "=r"(r[3]) : "r"(addr));
}

__device__ __forceinline__ void mma16816(float (&c)[4], const uint32_t (&a)[4],
                                         uint32_t b0, uint32_t b1) {
    asm volatile(
        "mma.sync.aligned.m16n8k16.row.col.f32.f16.f16.f32 "
        "{%0,%1,%2,%3}, {%4,%5,%6,%7}, {%8,%9}, {%0,%1,%2,%3};"
        : "+f"(c[0]), "+f"(c[1]), "+f"(c[2]), "+f"(c[3])
        : "r"(a[0]), "r"(a[1]), "r"(a[2]), "r"(a[3]), "r"(b0), "r"(b1));
}

__device__ __forceinline__ uint32_t pack_f16x2(float e, float o) {
    uint32_t r;
    asm("cvt.rn.satfinite.f16x2.f32 %0, %1, %2;" : "=r"(r) : "f"(o), "f"(e));
    return r;
}

// swizzled byte offset: row stride 256B, 16B-chunk XOR swizzle
__device__ __forceinline__ uint32_t mswz(int row, int k) {
    return (uint32_t)row * 256u + (((uint32_t)k * 2u) ^ (((uint32_t)row & 7u) << 4));
}

// group-scoped named barrier (ids 1,2; 256 threads each)
__device__ __forceinline__ void gbar(int id) {
    asm volatile("bar.sync %0, %1;" :: "r"(id), "r"(256) : "memory");
}

// ============================================================================
// Kernel 1: lengths — warp-parallel 3-probe search + compact work queue
// ============================================================================
__device__ __forceinline__ bool row_is_pad(const float* xb, int row) {
    float4 v = __ldg((const float4*)(xb + (size_t)row * FF));
    return (v.x == PADV) & (v.y == PADV) & (v.z == PADV) & (v.w == PADV);
}

__global__ void __launch_bounds__(256)
len_kernel(const float* __restrict__ x) {
    const int wid  = threadIdx.x >> 5;
    const int lane = threadIdx.x & 31;
    const int b = blockIdx.x * 8 + wid;
    if (b >= BB) return;
    const float* xb = x + (size_t)b * NN * FF;

    bool p1 = row_is_pad(xb, lane * 64);
    unsigned m1 = __ballot_sync(0xFFFFFFFFu, p1);
    int L;
    if (m1 == 0) L = 2048 - 64;
    else         L = (__ffs(m1) - 1 - 1) * 64;   // bit0 never set (len >= 1)

    bool p2 = row_is_pad(xb, L + 1 + 2 * lane);
    unsigned m2 = __ballot_sync(0xFFFFFFFFu, p2);
    int len;
    if (m2 == 0) {
        len = L + 64;
    } else {
        int t0 = __ffs(m2) - 1;
        bool pm = row_is_pad(xb, L + 2 * t0);
        unsigned mm = __ballot_sync(0xFFFFFFFFu, pm);
        len = (mm & 1u) ? (L + 2 * t0) : (L + 2 * t0 + 1);
    }
    if (lane == 0) {
        g_len[b] = len;
        int nt = (len + 63) >> 6;                 // 64-row units
        int base = atomicAdd(&g_nwork, nt);
        for (int t = 0; t < nt; t++) g_work[base + t] = (b << 5) | t;
    }
}

// ============================================================================
// Kernel 2: persistent phi — fp16 mma.sync; TWO independent 8-warp tile
// pipelines per CTA (named barriers), shared SMEM-resident weights.
// ============================================================================
__global__ void __launch_bounds__(PHI_THREADS, 1)
phi_kernel(const float* __restrict__ x,
           const float* __restrict__ w0, const float* __restrict__ b0,
           const float* __restrict__ w1, const float* __restrict__ b1,
           const float* __restrict__ w2, const float* __restrict__ b2,
           const float* __restrict__ w3, const float* __restrict__ b3) {
    extern __shared__ __align__(1024) char smem[];
    const int tid  = threadIdx.x;
    const int wid  = tid >> 5;
    const int lane = tid & 31;
    const int gid  = wid >> 3;          // pipeline group 0/1
    const int ltid = tid & 255;         // tid within group
    const int lwid = wid & 7;           // warp within group
    const int rg   = lwid >> 1;         // row-group 0..3 (16 rows each)
    const int ch   = lwid & 1;          // col-half 0..1 (64 cols each)
    const int barid = gid + 1;
    const uint32_t smem_base = smem_to_u32(smem);

    // ---- biases to SMEM ----
    {
        float* bs = (float*)(smem + BIAS_OFF);
        if (tid < HH) {
            bs[tid]          = b0[tid];
            bs[HH + tid]     = b1[tid];
            bs[2 * HH + tid] = b2[tid];
            bs[3 * HH + tid] = b3[tid];
        }
    }
    // ---- W1..W3 -> fp16, W[n][k] swizzled layout (shared by both groups) ----
    {
        const float* Wg[3] = { w1, w2, w3 };
        const int    Wo[3] = { W1_OFF, W2_OFF, W3_OFF };
        for (int Li = 0; Li < 3; Li++) {
            const float* W = Wg[Li];
            for (int i = tid; i < HH * HH; i += PHI_THREADS) {
                int k = i >> 7, n = i & 127;
                *reinterpret_cast<__half*>(smem + Wo[Li] + mswz(n, k)) = __float2half(W[i]);
            }
        }
    }
    // ---- W0 [16][128] -> fp16 W0[n][k], 48B row stride ----
    for (int i = tid; i < FF * HH; i += PHI_THREADS) {
        int k = i >> 7, n = i & 127;
        *reinterpret_cast<__half*>(smem + W0_OFF + n * 48 + k * 2) = __float2half(w0[i]);
    }
    __syncthreads();    // only full-CTA sync; groups are independent below

    const float* bias = (const float*)(smem + BIAS_OFF);
    const int GB = GRP_OFF + gid * GRP_SZ;
    int* s_slot = (int*)(smem + GB + GSLOT_OFF);
    float* red  = (float*)(smem + GB + GRED_OFF);
    const uint32_t WB[3] = { smem_base + W1_OFF, smem_base + W2_OFF, smem_base + W3_OFF };
    const uint32_t W0b = smem_base + W0_OFF;
    const uint32_t A2b = smem_base + GB + GA2_OFF;
    const uint32_t AB[2] = { smem_base + GB + GAP0_OFF, smem_base + GB + GAP1_OFF };

    // per-thread fragment coordinates (rows within the 64-row unit)
    const int ar = rg * 16 + (lane & 15);             // ldsm A row
    const int akh = (lane >> 4) << 3;                 // ldsm A k-offset (0/8)
    const int bn = ch * 64 + (lane & 7) + ((lane >> 4) << 3);  // ldsm B n base (+p*16)
    const int bk = ((lane >> 3) & 1) << 3;            // ldsm B k-offset (0/8)
    const int r0 = rg * 16 + (lane >> 2);             // C row (frag rows r0, r0+8)
    const int cc0 = ch * 64 + (lane & 3) * 2;         // C col base (+nb*8)
    const int xrow = ltid >> 2, xseg = ltid & 3;      // staging coords (64 rows x 4 segs)

    while (true) {
        gbar(barid);                    // protects s_slot + buffer reuse (group scope)
        if (ltid == 0) *s_slot = atomicAdd(&g_ticket, 1);
        gbar(barid);
        const int idx = *s_slot;
        if (idx >= g_nwork) break;
        const int slot = g_work[idx];
        const int b = slot >> 5, t = slot & 31;
        const int valid = min(64, g_len[b] - t * 64);
        const bool wact = (rg * 16 < valid);   // warp's 16-row group has valid rows

        // ---- stage x unit -> A2 as fp16 (48B stride), zero invalid rows ----
        {
            float4 v = __ldg((const float4*)(x + ((size_t)b * NN + t * 64 + xrow) * FF + xseg * 4));
            uint32_t p0 = 0, p1 = 0;
            if (xrow < valid) { p0 = pack_f16x2(v.x, v.y); p1 = pack_f16x2(v.z, v.w); }
            *(uint32_t*)(smem + GB + GA2_OFF + xrow * 48 + xseg * 8)     = p0;
            *(uint32_t*)(smem + GB + GA2_OFF + xrow * 48 + xseg * 8 + 4) = p1;
        }
        gbar(barid);

        float c[8][4];

        // ---- layer 0: K=16 MMA from A2 x W0, bias0+ReLU -> AP0 ----
        if (wact) {
            #pragma unroll
            for (int nb = 0; nb < 8; nb++)
                #pragma unroll
                for (int j = 0; j < 4; j++) c[nb][j] = 0.f;
            uint32_t a[4];
            ldsm4(a, A2b + ar * 48 + akh * 2);
            #pragma unroll
            for (int p = 0; p < 4; p++) {
                uint32_t bh[4];
                ldsm4(bh, W0b + (bn + p * 16) * 48 + bk * 2);
                mma16816(c[2 * p],     a, bh[0], bh[1]);
                mma16816(c[2 * p + 1], a, bh[2], bh[3]);
            }
            const float* bl_ = bias;    // b0
            #pragma unroll
            for (int nb = 0; nb < 8; nb++) {
                int col = cc0 + nb * 8;
                float be = bl_[col], bo = bl_[col + 1];
                uint32_t p0 = pack_f16x2(fmaxf(c[nb][0] + be, 0.f), fmaxf(c[nb][1] + bo, 0.f));
                uint32_t p1 = pack_f16x2(fmaxf(c[nb][2] + be, 0.f), fmaxf(c[nb][3] + bo, 0.f));
                *(uint32_t*)(smem + GB + GAP0_OFF + mswz(r0, col))     = p0;
                *(uint32_t*)(smem + GB + GAP0_OFF + mswz(r0 + 8, col)) = p1;
            }
        }
        gbar(barid);

        // ---- layers 1..3: fp16 MMA, ping-pong activations (group-local) ----
        #pragma unroll
        for (int L = 0; L < 3; L++) {
            const uint32_t Acur = AB[L & 1];
            const uint32_t Wb = WB[L];
            if (wact) {
                #pragma unroll
                for (int nb = 0; nb < 8; nb++)
                    #pragma unroll
                    for (int j = 0; j < 4; j++) c[nb][j] = 0.f;
                #pragma unroll
                for (int kb = 0; kb < 8; kb++) {
                    uint32_t a[4];
                    ldsm4(a, Acur + mswz(ar, kb * 16 + akh));
                    #pragma unroll
                    for (int p = 0; p < 4; p++) {
                        uint32_t bh[4];
                        ldsm4(bh, Wb + mswz(bn + p * 16, kb * 16 + bk));
                        mma16816(c[2 * p],     a, bh[0], bh[1]);
                        mma16816(c[2 * p + 1], a, bh[2], bh[3]);
                    }
                }
            }

            if (L < 2) {
                if (wact) {
                    const float* bl_ = bias + (L + 1) * HH;
                    const uint32_t Anxt = (uint32_t)(GB + ((L & 1) ? GAP0_OFF : GAP1_OFF));
                    #pragma unroll
                    for (int nb = 0; nb < 8; nb++) {
                        int col = cc0 + nb * 8;
                        float be = bl_[col], bo = bl_[col + 1];
                        uint32_t p0 = pack_f16x2(fmaxf(c[nb][0] + be, 0.f), fmaxf(c[nb][1] + bo, 0.f));
                        uint32_t p1 = pack_f16x2(fmaxf(c[nb][2] + be, 0.f), fmaxf(c[nb][3] + bo, 0.f));
                        *(uint32_t*)(smem + Anxt + mswz(r0, col))     = p0;
                        *(uint32_t*)(smem + Anxt + mswz(r0 + 8, col)) = p1;
                    }
                }
                gbar(barid);
            } else {
                // final: bias + ReLU + masked column-sum (pooling partial)
                if (wact) {
                    const float* b3s = bias + 3 * HH;
                    const float m0 = (r0 < valid) ? 1.f : 0.f;
                    const float m1 = (r0 + 8 < valid) ? 1.f : 0.f;
                    #pragma unroll
                    for (int nb = 0; nb < 8; nb++) {
                        int col = cc0 + nb * 8;
                        float be = b3s[col], bo = b3s[col + 1];
                        float s0 = m0 * fmaxf(c[nb][0] + be, 0.f) + m1 * fmaxf(c[nb][2] + be, 0.f);
                        float s1 = m0 * fmaxf(c[nb][1] + bo, 0.f) + m1 * fmaxf(c[nb][3] + bo, 0.f);
                        #pragma unroll
                        for (int off = 4; off < 32; off <<= 1) {
                            s0 += __shfl_xor_sync(0xFFFFFFFFu, s0, off);
                            s1 += __shfl_xor_sync(0xFFFFFFFFu, s1, off);
                        }
                        if (lane < 4) {
                            int cc = ch * 64 + nb * 8 + lane * 2;
                            red[rg * HH + cc]     = s0;
                            red[rg * HH + cc + 1] = s1;
                        }
                    }
                } else {
                    if (lane < 4) {
                        #pragma unroll
                        for (int nb = 0; nb < 8; nb++) {
                            int cc = ch * 64 + nb * 8 + lane * 2;
                            red[rg * HH + cc]     = 0.f;
                            red[rg * HH + cc + 1] = 0.f;
                        }
                    }
                }
                gbar(barid);
                if (ltid < HH) {
                    float s = red[ltid] + red[HH + ltid] + red[2 * HH + ltid] + red[3 * HH + ltid];
                    g_partial[(size_t)slot * HH + ltid] = s;
                }
            }
        }
    }
}

// ============================================================================
// Kernel 3: rho (fp32 SIMT) — 1 batch/block (512 blocks), K split across 2
// thread-halves; resets counters at the tail.
// ============================================================================
__global__ void __launch_bounds__(256)
rho_kernel(const float* __restrict__ w0, const float* __restrict__ b0,
           const float* __restrict__ w1, const float* __restrict__ b1,
           const float* __restrict__ w2, const float* __restrict__ b2,
           const float* __restrict__ w3, const float* __restrict__ b3,
           float* __restrict__ out) {
    __shared__ float s_in[HH];
    __shared__ float s_part[2][HH];
    const int b = blockIdx.x;
    const int j = threadIdx.x & 127;
    const int h = threadIdx.x >> 7;           // k-half 0/1

    // fixed-split pooling of per-unit partials (deterministic)
    {
        const int nt = (g_len[b] + 63) >> 6;
        float acc = 0.f;
        for (int t = h; t < nt; t += 2)
            acc += g_partial[((size_t)b * TILES2 + t) * HH + j];
        s_part[h][j] = acc;
    }
    __syncthreads();
    if (h == 0) s_in[j] = s_part[0][j] + s_part[1][j];
    __syncthreads();

    const float* Ws[3] = { w0, w1, w2 };
    const float* Bs[3] = { b0, b1, b2 };
    #pragma unroll
    for (int L = 0; L < 3; L++) {
        const float* W = Ws[L] + (size_t)h * 64 * HH;
        float p = 0.f;
        #pragma unroll 16
        for (int kk = 0; kk < 64; kk++)
            p = fmaf(s_in[h * 64 + kk], __ldg(W + kk * HH + j), p);
        s_part[h][j] = p;
        __syncthreads();
        if (h == 0) s_in[j] = fmaxf(s_part[0][j] + s_part[1][j] + Bs[L][j], 0.f);
        __syncthreads();
    }

    if (h == 0) s_part[0][j] = s_in[j] * __ldg(w3 + j);
    __syncthreads();
    if (threadIdx.x < 32) {
        const int lane = threadIdx.x;
        float s = s_part[0][lane] + s_part[0][lane + 32]
                + s_part[0][lane + 64] + s_part[0][lane + 96];
        #pragma unroll
        for (int off = 16; off > 0; off >>= 1)
            s += __shfl_xor_sync(0xFFFFFFFFu, s, off);
        if (lane == 0) out[b] = s + __ldg(b3);
    }

    // tail reset for the next graph replay
    if (b == 0 && threadIdx.x == 0) { g_ticket = 0; g_nwork = 0; }
}

// ============================================================================
// kernel_launch
// ============================================================================
extern "C" void kernel_launch(void* const* d_in, const int* in_sizes, int n_in,
                              void* d_out, int out_size) {
    const float* x   = (const float*)d_in[0];
    const float* pw0 = (const float*)d_in[1];
    const float* pb0 = (const float*)d_in[2];
    const float* pw1 = (const float*)d_in[3];
    const float* pb1 = (const float*)d_in[4];
    const float* pw2 = (const float*)d_in[5];
    const float* pb2 = (const float*)d_in[6];
    const float* pw3 = (const float*)d_in[7];
    const float* pb3 = (const float*)d_in[8];
    const float* rw0 = (const float*)d_in[9];
    const float* rb0 = (const float*)d_in[10];
    const float* rw1 = (const float*)d_in[11];
    const float* rb1 = (const float*)d_in[12];
    const float* rw2 = (const float*)d_in[13];
    const float* rb2 = (const float*)d_in[14];
    const float* rw3 = (const float*)d_in[15];
    const float* rb3 = (const float*)d_in[16];

    static bool attr_set = false;
    if (!attr_set) {
        cudaFuncSetAttribute(phi_kernel, cudaFuncAttributeMaxDynamicSharedMemorySize, SMEM_TOTAL);
        attr_set = true;
    }

    len_kernel<<<BB / 8, 256>>>(x);
    phi_kernel<<<PHI_GRID, PHI_THREADS, SMEM_TOTAL>>>(x, pw0, pb0, pw1, pb1, pw2, pb2, pw3, pb3);
    rho_kernel<<<BB, 256>>>(rw0, rb0, rw1, rb1, rw2, rb2, rw3, rb3, (float*)d_out);
}